// round 1
// baseline (speedup 1.0000x reference)
#include <cuda_runtime.h>

// Scalar accumulator in device global (no allocations allowed).
__device__ double g_acc;

__global__ void k_reset() { g_acc = 0.0; }

// Exact angular-order comparator equivalent to atan2(y,x) ascending in (-pi, pi].
// half 0: y<0, or (y==0 && x>=0)  -> angle in (-pi, 0]
// half 1: y>0, or (y==0 && x<0)   -> angle in (0, pi]
__device__ __forceinline__ bool ang_less(float ax, float ay, float bx, float by) {
    bool ha = (ay > 0.f) || (ay == 0.f && ax < 0.f);
    bool hb = (by > 0.f) || (by == 0.f && bx < 0.f);
    if (ha != hb) return hb;              // a in lower half, b in upper -> a < b
    return (ax * by - ay * bx) > 0.f;     // within a half-plane, cross sign decides
}

__global__ void __launch_bounds__(256)
k_loss(const float* __restrict__ pred, const float* __restrict__ target, int n) {
    int i = blockIdx.x * blockDim.x + threadIdx.x;
    float loss = 0.f;
    if (i < n) {
        const float* P = pred + 5 * (long)i;
        const float* T = target + 5 * (long)i;
        float px = P[0], py = P[1], pw = P[2], ph = P[3], pa = P[4];
        float tx = T[0], ty = T[1], tw = T[2], th = T[3], ta = T[4];
        float sp, cp, st, ct;
        sincosf(pa, &sp, &cp);
        sincosf(ta, &st, &ct);

        const float DX[4] = {0.5f, -0.5f, -0.5f, 0.5f};
        const float DY[4] = {0.5f, 0.5f, -0.5f, -0.5f};
        float c1x[4], c1y[4], c2x[4], c2y[4];
#pragma unroll
        for (int j = 0; j < 4; j++) {
            float dx = DX[j] * pw, dy = DY[j] * ph;
            c1x[j] = dx * cp - dy * sp + px;
            c1y[j] = dx * sp + dy * cp + py;
            float ex = DX[j] * tw, ey = DY[j] * th;
            c2x[j] = ex * ct - ey * st + tx;
            c2y[j] = ex * st + ey * ct + ty;
        }

        // Collect valid vertices in reference order: c1 corners, c2 corners,
        // then 4x4 edge intersections (c1-edge major). Stability of the later
        // sort relies on this collection order.
        float vx[24], vy[24];
        int k = 0;
        {   // corners of c1 inside box2
            float ax = c2x[0], ay = c2y[0];
            float abx = c2x[1] - ax, aby = c2y[1] - ay;
            float adx = c2x[3] - ax, ady = c2y[3] - ay;
            float iab = __fdividef(1.f, abx * abx + aby * aby);
            float iad = __fdividef(1.f, adx * adx + ady * ady);
#pragma unroll
            for (int j = 0; j < 4; j++) {
                float amx = c1x[j] - ax, amy = c1y[j] - ay;
                float pab = (abx * amx + aby * amy) * iab;
                float pad = (adx * amx + ady * amy) * iad;
                const float e = 1e-6f;
                if (pab > -e && pab < 1.f + e && pad > -e && pad < 1.f + e) {
                    vx[k] = c1x[j]; vy[k] = c1y[j]; k++;
                }
            }
        }
        {   // corners of c2 inside box1
            float ax = c1x[0], ay = c1y[0];
            float abx = c1x[1] - ax, aby = c1y[1] - ay;
            float adx = c1x[3] - ax, ady = c1y[3] - ay;
            float iab = __fdividef(1.f, abx * abx + aby * aby);
            float iad = __fdividef(1.f, adx * adx + ady * ady);
#pragma unroll
            for (int j = 0; j < 4; j++) {
                float amx = c2x[j] - ax, amy = c2y[j] - ay;
                float pab = (abx * amx + aby * amy) * iab;
                float pad = (adx * amx + ady * amy) * iad;
                const float e = 1e-6f;
                if (pab > -e && pab < 1.f + e && pad > -e && pad < 1.f + e) {
                    vx[k] = c2x[j]; vy[k] = c2y[j]; k++;
                }
            }
        }
#pragma unroll
        for (int a = 0; a < 4; a++) {
            int a2 = (a + 1) & 3;
            float x1 = c1x[a], y1 = c1y[a];
            float ex = c1x[a2] - x1, ey = c1y[a2] - y1;
#pragma unroll
            for (int b = 0; b < 4; b++) {
                int b2 = (b + 1) & 3;
                float x3 = c2x[b], y3 = c2y[b];
                float fx = c2x[b2] - x3, fy = c2y[b2] - y3;
                float num = fy * ex - fx * ey;
                if (num != 0.f) {
                    float dxs = x1 - x3, dys = y1 - y3;
                    float den_t = fx * dys - fy * dxs;
                    float den_u = ex * dys - ey * dxs;
                    float inv = __fdividef(1.f, num);
                    float t = den_t * inv;
                    float u = -den_u * inv;
                    if (t > 0.f && t < 1.f && u > 0.f && u < 1.f) {
                        float t2 = __fdividef(den_t, num + 1e-8f);
                        vx[k] = x1 + t2 * ex;
                        vy[k] = y1 + t2 * ey;
                        k++;
                    }
                }
            }
        }

        // Centroid of valid vertices (reference: sum / max(k,1))
        float sx = 0.f, sy = 0.f;
        for (int j = 0; j < k; j++) { sx += vx[j]; sy += vy[j]; }
        float invk = __fdividef(1.f, fmaxf((float)k, 1.f));
        float mx = sx * invk, my = sy * invk;

        // Stable insertion sort by angle around centroid (matches stable argsort).
        for (int j = 1; j < k; j++) {
            float kx = vx[j], ky = vy[j];
            float rx = kx - mx, ry = ky - my;
            int l = j - 1;
            while (l >= 0 && ang_less(rx, ry, vx[l] - mx, vy[l] - my)) {
                vx[l + 1] = vx[l]; vy[l + 1] = vy[l];
                l--;
            }
            vx[l + 1] = kx; vy[l + 1] = ky;
        }

        // Shoelace over the k sorted vertices (uncentered coords, like reference).
        float area2 = 0.f;
        for (int j = 0; j < k; j++) {
            int jn = (j + 1 < k) ? j + 1 : 0;
            area2 += vx[j] * vy[jn] - vy[j] * vx[jn];
        }
        float inter = fabsf(area2) * 0.5f;

        float a1 = pw * ph, a2b = tw * th;
        float iou = __fdividef(inter, a1 + a2b - inter);
        iou = fmaxf(iou, 1e-6f);

        // Sort 4 corners of each box by x (stable).
        float psx[4], psy[4], gsx[4], gsy[4];
#pragma unroll
        for (int j = 0; j < 4; j++) { psx[j] = c1x[j]; psy[j] = c1y[j]; gsx[j] = c2x[j]; gsy[j] = c2y[j]; }
#pragma unroll
        for (int j = 1; j < 4; j++) {
            float kx = psx[j], ky = psy[j];
            int l = j - 1;
            while (l >= 0 && psx[l] > kx) { psx[l + 1] = psx[l]; psy[l + 1] = psy[l]; l--; }
            psx[l + 1] = kx; psy[l + 1] = ky;
        }
#pragma unroll
        for (int j = 1; j < 4; j++) {
            float kx = gsx[j], ky = gsy[j];
            int l = j - 1;
            while (l >= 0 && gsx[l] > kx) { gsx[l + 1] = gsx[l]; gsy[l + 1] = gsy[l]; l--; }
            gsx[l + 1] = kx; gsy[l + 1] = ky;
        }

        float d0 = gsx[0] - psx[0];
        float d = 2.f * d0 * d0;
#pragma unroll
        for (int j = 1; j < 4; j++) {
            float ddx = psx[j] - gsx[j];
            float ddy = psy[j] - gsy[j];
            d += ddx * ddx + ddy * ddy;
        }
        float res = d * (1.f / (4.f * 1024.f * 1024.f));
        loss = 1.f - iou + res;
    }

    // Block reduction -> double atomic
    for (int o = 16; o > 0; o >>= 1)
        loss += __shfl_down_sync(0xffffffffu, loss, o);
    __shared__ float ssum[8];
    int lane = threadIdx.x & 31, wid = threadIdx.x >> 5;
    if (lane == 0) ssum[wid] = loss;
    __syncthreads();
    if (wid == 0) {
        float v = (lane < (int)(blockDim.x >> 5)) ? ssum[lane] : 0.f;
        for (int o = 4; o > 0; o >>= 1)
            v += __shfl_down_sync(0xffffffffu, v, o);
        if (lane == 0) atomicAdd(&g_acc, (double)v);
    }
}

__global__ void k_finalize(float* out, int n) {
    out[0] = (float)(g_acc / (double)n);
}

extern "C" void kernel_launch(void* const* d_in, const int* in_sizes, int n_in,
                              void* d_out, int out_size) {
    (void)n_in; (void)out_size;
    const float* pred = (const float*)d_in[0];
    const float* target = (const float*)d_in[1];
    int n = in_sizes[0] / 5;
    k_reset<<<1, 1>>>();
    int threads = 256;
    int blocks = (n + threads - 1) / threads;
    k_loss<<<blocks, threads>>>(pred, target, n);
    k_finalize<<<1, 1>>>((float*)d_out, n);
}

// round 4
// speedup vs baseline: 1.1200x; 1.1200x over previous
#include <cuda_runtime.h>

#define MAXBLK 16384
__device__ float g_part[MAXBLK];
__device__ unsigned g_ctr = 0;

// Monotone pseudo-angle: same ordering as atan2(y,x) on (-pi, pi].
// y>0 -> (0,2], y<0 -> (-2,0), y=+0,x>0 -> 0, y=+0,x<0 -> +2 (== +pi). Ties measure-zero.
__device__ __forceinline__ float diamond_key(float x, float y) {
    float s = fabsf(x) + fabsf(y);
    float r = __fdividef(x, s);
    float key = copysignf(1.f - r, y);
    return (s > 0.f) ? key : 0.f;
}

// branch-free compare-exchange on (x,y) keyed by x
#define CE(xi, yi, xj, yj)                          \
    {                                               \
        bool p_ = (xi) > (xj);                      \
        float tx_ = (xi), ty_ = (yi);               \
        (xi) = p_ ? (xj) : (xi);                    \
        (yi) = p_ ? (yj) : (yi);                    \
        (xj) = p_ ? tx_ : (xj);                     \
        (yj) = p_ ? ty_ : (yj);                     \
    }

__global__ void __launch_bounds__(256)
k_loss(const float* __restrict__ pred, const float* __restrict__ target,
       float* __restrict__ out, int n, int nblk)
{
    float loss = 0.f;
    for (int i = blockIdx.x * blockDim.x + threadIdx.x; i < n;
         i += gridDim.x * blockDim.x) {
        const float* P = pred + 5l * i;
        const float* T = target + 5l * i;
        float px = P[0], py = P[1], pw = P[2], ph = P[3], pa = P[4];
        float tx = T[0], ty = T[1], tw = T[2], th = T[3], ta = T[4];
        float sp, cp, st, ct;
        __sincosf(pa, &sp, &cp);
        __sincosf(ta, &st, &ct);

        const float DX[4] = {0.5f, -0.5f, -0.5f, 0.5f};
        const float DY[4] = {0.5f, 0.5f, -0.5f, -0.5f};
        // Corners in box1-centered frame (all downstream math shift-invariant).
        float ox = tx - px, oy = ty - py;
        float c1x[4], c1y[4], c2x[4], c2y[4];
#pragma unroll
        for (int j = 0; j < 4; j++) {
            float dx = DX[j] * pw, dy = DY[j] * ph;
            c1x[j] = dx * cp - dy * sp;
            c1y[j] = dx * sp + dy * cp;
            float ex = DX[j] * tw, ey = DY[j] * th;
            c2x[j] = ex * ct - ey * st + ox;
            c2y[j] = ex * st + ey * ct + oy;
        }

        // ---- Collect valid vertices in reference order ----
        float2 va[16];
        float ky[16];
        int k = 0;
        {   // corners of c1 inside box2
            float ax = c2x[0], ay = c2y[0];
            float abx = c2x[1] - ax, aby = c2y[1] - ay;
            float adx = c2x[3] - ax, ady = c2y[3] - ay;
            float iab = __fdividef(1.f, abx * abx + aby * aby);
            float iad = __fdividef(1.f, adx * adx + ady * ady);
#pragma unroll
            for (int j = 0; j < 4; j++) {
                float amx = c1x[j] - ax, amy = c1y[j] - ay;
                float pab = (abx * amx + aby * amy) * iab;
                float pad = (adx * amx + ady * amy) * iad;
                const float e = 1e-6f;
                if (pab > -e && pab < 1.f + e && pad > -e && pad < 1.f + e) {
                    va[k] = make_float2(c1x[j], c1y[j]); k++;
                }
            }
        }
        {   // corners of c2 inside box1
            float ax = c1x[0], ay = c1y[0];
            float abx = c1x[1] - ax, aby = c1y[1] - ay;
            float adx = c1x[3] - ax, ady = c1y[3] - ay;
            float iab = __fdividef(1.f, abx * abx + aby * aby);
            float iad = __fdividef(1.f, adx * adx + ady * ady);
#pragma unroll
            for (int j = 0; j < 4; j++) {
                float amx = c2x[j] - ax, amy = c2y[j] - ay;
                float pab = (abx * amx + aby * amy) * iab;
                float pad = (adx * amx + ady * amy) * iad;
                const float e = 1e-6f;
                if (pab > -e && pab < 1.f + e && pad > -e && pad < 1.f + e) {
                    va[k] = make_float2(c2x[j], c2y[j]); k++;
                }
            }
        }
#pragma unroll
        for (int a = 0; a < 4; a++) {
            int a2 = (a + 1) & 3;
            float x1 = c1x[a], y1 = c1y[a];
            float ex = c1x[a2] - x1, ey = c1y[a2] - y1;
#pragma unroll
            for (int b = 0; b < 4; b++) {
                int b2 = (b + 1) & 3;
                float x3 = c2x[b], y3 = c2y[b];
                float fx = c2x[b2] - x3, fy = c2y[b2] - y3;
                float num = fy * ex - fx * ey;
                if (num != 0.f) {
                    float dxs = x1 - x3, dys = y1 - y3;
                    float den_t = fx * dys - fy * dxs;
                    float den_u = ex * dys - ey * dxs;
                    float inv = __fdividef(1.f, num);
                    float t = den_t * inv;
                    float u = -den_u * inv;
                    if (t > 0.f && t < 1.f && u > 0.f && u < 1.f) {
                        float t2 = __fdividef(den_t, num + 1e-8f);
                        va[k] = make_float2(x1 + t2 * ex, y1 + t2 * ey);
                        k++;
                    }
                }
            }
        }

        // ---- Centroid of valid vertices ----
        float sx = 0.f, sy = 0.f;
        for (int j = 0; j < k; j++) { sx += va[j].x; sy += va[j].y; }
        float invk = __fdividef(1.f, fmaxf((float)k, 1.f));
        float mx = sx * invk, my = sy * invk;

        // ---- Pseudo-angle keys (once per vertex) ----
        for (int j = 0; j < k; j++)
            ky[j] = diamond_key(va[j].x - mx, va[j].y - my);

        // ---- Stable insertion sort by key (matches stable argsort of atan2) ----
        for (int j = 1; j < k; j++) {
            float kj = ky[j];
            float2 vj = va[j];
            int l = j - 1;
            while (l >= 0 && ky[l] > kj) {
                ky[l + 1] = ky[l]; va[l + 1] = va[l];
                l--;
            }
            ky[l + 1] = kj; va[l + 1] = vj;
        }

        // ---- Shoelace over the k sorted vertices ----
        float area2 = 0.f;
        for (int j = 0; j < k; j++) {
            int jn = (j + 1 < k) ? j + 1 : 0;
            area2 += va[j].x * va[jn].y - va[j].y * va[jn].x;
        }
        float inter = fabsf(area2) * 0.5f;

        float iou = __fdividef(inter, pw * ph + tw * th - inter);
        iou = fmaxf(iou, 1e-6f);

        // ---- Residual: x-sort corners of each box (5-CE networks) ----
        float ax0 = c1x[0], ay0 = c1y[0], ax1 = c1x[1], ay1 = c1y[1];
        float ax2 = c1x[2], ay2 = c1y[2], ax3 = c1x[3], ay3 = c1y[3];
        CE(ax0, ay0, ax1, ay1) CE(ax2, ay2, ax3, ay3)
        CE(ax0, ay0, ax2, ay2) CE(ax1, ay1, ax3, ay3)
        CE(ax1, ay1, ax2, ay2)
        float bx0 = c2x[0], by0 = c2y[0], bx1 = c2x[1], by1 = c2y[1];
        float bx2 = c2x[2], by2 = c2y[2], bx3 = c2x[3], by3 = c2y[3];
        CE(bx0, by0, bx1, by1) CE(bx2, by2, bx3, by3)
        CE(bx0, by0, bx2, by2) CE(bx1, by1, bx3, by3)
        CE(bx1, by1, bx2, by2)

        float d0 = bx0 - ax0;
        float d = 2.f * d0 * d0;
        float q1x = ax1 - bx1, q1y = ay1 - by1;
        float q2x = ax2 - bx2, q2y = ay2 - by2;
        float q3x = ax3 - bx3, q3y = ay3 - by3;
        d += q1x * q1x + q1y * q1y;
        d += q2x * q2x + q2y * q2y;
        d += q3x * q3x + q3y * q3y;
        float res = d * (1.f / (4.f * 1024.f * 1024.f));
        loss += 1.f - iou + res;
    }

    // ---- Block reduction -> per-block partial ----
#pragma unroll
    for (int o = 16; o > 0; o >>= 1)
        loss += __shfl_down_sync(0xffffffffu, loss, o);
    __shared__ float ssum[8];
    __shared__ bool is_last;
    int lane = threadIdx.x & 31, wid = threadIdx.x >> 5;
    if (lane == 0) ssum[wid] = loss;
    __syncthreads();
    if (threadIdx.x == 0) {
        float v = 0.f;
#pragma unroll
        for (int w = 0; w < 8; w++) v += ssum[w];
        g_part[blockIdx.x] = v;
        __threadfence();
        unsigned old = atomicAdd(&g_ctr, 1u);
        is_last = (old == (unsigned)(gridDim.x - 1));
    }
    __syncthreads();

    // ---- Last block finalizes (single kernel, graph-replay safe) ----
    if (is_last) {
        double s = 0.0;
        for (int j = threadIdx.x; j < nblk; j += blockDim.x)
            s += (double)__ldcg(&g_part[j]);
        __shared__ double sd[256];
        sd[threadIdx.x] = s;
        __syncthreads();
#pragma unroll
        for (int o = 128; o > 0; o >>= 1) {
            if (threadIdx.x < o) sd[threadIdx.x] += sd[threadIdx.x + o];
            __syncthreads();
        }
        if (threadIdx.x == 0) {
            out[0] = (float)(sd[0] / (double)n);
            g_ctr = 0;  // reset for next graph replay
        }
    }
}

extern "C" void kernel_launch(void* const* d_in, const int* in_sizes, int n_in,
                              void* d_out, int out_size)
{
    (void)n_in; (void)out_size;
    const float* pred = (const float*)d_in[0];
    const float* target = (const float*)d_in[1];
    int n = in_sizes[0] / 5;
    int threads = 256;
    int blocks = (n + threads - 1) / threads;
    if (blocks > MAXBLK) blocks = MAXBLK;  // grid-stride covers remainder
    k_loss<<<blocks, threads>>>(pred, target, (float*)d_out, n, blocks);
}

// round 5
// speedup vs baseline: 1.3635x; 1.2173x over previous
#include <cuda_runtime.h>

#define MAXBLK 16384
#define BT 256
__device__ float g_part[MAXBLK];
__device__ unsigned g_ctr = 0;

// branch-free compare-exchange on (x,y) keyed by x
#define CE(xi, yi, xj, yj)                          \
    {                                               \
        bool p_ = (xi) > (xj);                      \
        float tx_ = (xi), ty_ = (yi);               \
        (xi) = p_ ? (xj) : (xi);                    \
        (yi) = p_ ? (yj) : (yi);                    \
        (xj) = p_ ? tx_ : (xj);                     \
        (yj) = p_ ? ty_ : (yj);                     \
    }

// uint compare-exchange: 2x IMNMX
#define CEU(a, b) { unsigned lo_ = umin(a, b), hi_ = umax(a, b); a = lo_; b = hi_; }

// Sortable key: diamond pseudo-angle (monotone bijection with atan2(y,x) on
// (-pi,pi], incl. the y==+/-0 edge cases), mapped to order-preserving uint,
// low 4 bits replaced by slot index for stable tiebreak in reference order.
__device__ __forceinline__ unsigned sort_key(float x, float y, unsigned j) {
    float s = fabsf(x) + fabsf(y);
    float r = __fdividef(x, s);
    float key = copysignf(1.f - r, y);   // y>0:(0,2], y<0:(-2,0), +/-0 at 0
    key = (s > 0.f) ? key : 0.f;         // vertex==centroid -> angle 0 (atan2(0,0)=0)
    unsigned u = __float_as_uint(key);
    u = ((int)u < 0) ? ~u : (u | 0x80000000u);
    return (u & ~15u) | j;
}

__global__ void __launch_bounds__(BT)
k_loss(const float* __restrict__ pred, const float* __restrict__ target,
       float* __restrict__ out, int n, int nblk)
{
    __shared__ float2 sverts[16][BT];   // column layout: conflict-free dynamic idx
    const int tid = threadIdx.x;

    float loss = 0.f;
    for (int i = blockIdx.x * blockDim.x + tid; i < n; i += gridDim.x * blockDim.x) {
        const float* P = pred + 5l * i;
        const float* T = target + 5l * i;
        float px = P[0], py = P[1], pw = P[2], ph = P[3], pa = P[4];
        float tx = T[0], ty = T[1], tw = T[2], th = T[3], ta = T[4];
        float sp, cp, st, ct;
        __sincosf(pa, &sp, &cp);
        __sincosf(ta, &st, &ct);

        const float DX[4] = {0.5f, -0.5f, -0.5f, 0.5f};
        const float DY[4] = {0.5f, 0.5f, -0.5f, -0.5f};
        // Box1-centered frame (masks/area/residual all shift-invariant).
        float ox = tx - px, oy = ty - py;
        float c1x[4], c1y[4], c2x[4], c2y[4];
#pragma unroll
        for (int j = 0; j < 4; j++) {
            float dx = DX[j] * pw, dy = DY[j] * ph;
            c1x[j] = dx * cp - dy * sp;
            c1y[j] = dx * sp + dy * cp;
            float ex = DX[j] * tw, ey = DY[j] * th;
            c2x[j] = ex * ct - ey * st + ox;
            c2y[j] = ex * st + ey * ct + oy;
        }

        // ---- Collect valid vertices (reference order) into smem; sums in regs ----
        int kc = 0;
        float sx = 0.f, sy = 0.f;
        {   // corners of c1 inside box2 (division-free: compare dots vs eps*|e|^2)
            float ax = c2x[0], ay = c2y[0];
            float abx = c2x[1] - ax, aby = c2y[1] - ay;
            float adx = c2x[3] - ax, ady = c2y[3] - ay;
            float nab = abx * abx + aby * aby;
            float nad = adx * adx + ady * ady;
            float lab = -1e-6f * nab, hab = (1.f + 1e-6f) * nab;
            float lad = -1e-6f * nad, had = (1.f + 1e-6f) * nad;
#pragma unroll
            for (int j = 0; j < 4; j++) {
                float amx = c1x[j] - ax, amy = c1y[j] - ay;
                float dab = abx * amx + aby * amy;
                float dad = adx * amx + ady * amy;
                if (dab > lab && dab < hab && dad > lad && dad < had && kc < 16) {
                    sverts[kc][tid] = make_float2(c1x[j], c1y[j]);
                    sx += c1x[j]; sy += c1y[j]; kc++;
                }
            }
        }
        {   // corners of c2 inside box1
            float ax = c1x[0], ay = c1y[0];
            float abx = c1x[1] - ax, aby = c1y[1] - ay;
            float adx = c1x[3] - ax, ady = c1y[3] - ay;
            float nab = abx * abx + aby * aby;
            float nad = adx * adx + ady * ady;
            float lab = -1e-6f * nab, hab = (1.f + 1e-6f) * nab;
            float lad = -1e-6f * nad, had = (1.f + 1e-6f) * nad;
#pragma unroll
            for (int j = 0; j < 4; j++) {
                float amx = c2x[j] - ax, amy = c2y[j] - ay;
                float dab = abx * amx + aby * amy;
                float dad = adx * amx + ady * amy;
                if (dab > lab && dab < hab && dad > lad && dad < had && kc < 16) {
                    sverts[kc][tid] = make_float2(c2x[j], c2y[j]);
                    sx += c2x[j]; sy += c2y[j]; kc++;
                }
            }
        }
#pragma unroll
        for (int a = 0; a < 4; a++) {
            int a2 = (a + 1) & 3;
            float x1 = c1x[a], y1 = c1y[a];
            float ex = c1x[a2] - x1, ey = c1y[a2] - y1;
#pragma unroll
            for (int b = 0; b < 4; b++) {
                int b2 = (b + 1) & 3;
                float x3 = c2x[b], y3 = c2y[b];
                float fx = c2x[b2] - x3, fy = c2y[b2] - y3;
                float num = fy * ex - fx * ey;
                float dxs = x1 - x3, dys = y1 - y3;
                float den_t = fx * dys - fy * dxs;
                float den_u = ex * dys - ey * dxs;
                // t = den_t/num in (0,1) and u = -den_u/num in (0,1), sans division
                bool m = (den_t * num > 0.f) & ((den_t - num) * num < 0.f)
                       & (den_u * num < 0.f) & ((den_u + num) * num > 0.f);
                if (m && kc < 16) {
                    float t2 = __fdividef(den_t, num + 1e-8f);
                    float vx = fmaf(t2, ex, x1), vy = fmaf(t2, ey, y1);
                    sverts[kc][tid] = make_float2(vx, vy);
                    sx += vx; sy += vy; kc++;
                }
            }
        }

        // ---- Centroid, then sortable angle keys (registers, static indices) ----
        float invk = __fdividef(1.f, fmaxf((float)kc, 1.f));
        float mx = sx * invk, my = sy * invk;
        unsigned ky[16];
#pragma unroll
        for (int j = 0; j < 16; j++) ky[j] = 0xFFFFFFFFu;
#pragma unroll 16
        for (int j = 0; j < 16; j++) {
            if (j >= kc) break;
            float2 v = sverts[j][tid];
            ky[j] = sort_key(v.x - mx, v.y - my, (unsigned)j);
        }

        // ---- Batcher odd-even merge sort, 16 elems, 63 CEs, branch-free ----
        CEU(ky[0],ky[1]) CEU(ky[2],ky[3]) CEU(ky[4],ky[5]) CEU(ky[6],ky[7])
        CEU(ky[8],ky[9]) CEU(ky[10],ky[11]) CEU(ky[12],ky[13]) CEU(ky[14],ky[15])
        CEU(ky[0],ky[2]) CEU(ky[1],ky[3]) CEU(ky[4],ky[6]) CEU(ky[5],ky[7])
        CEU(ky[8],ky[10]) CEU(ky[9],ky[11]) CEU(ky[12],ky[14]) CEU(ky[13],ky[15])
        CEU(ky[1],ky[2]) CEU(ky[5],ky[6]) CEU(ky[9],ky[10]) CEU(ky[13],ky[14])
        CEU(ky[0],ky[4]) CEU(ky[1],ky[5]) CEU(ky[2],ky[6]) CEU(ky[3],ky[7])
        CEU(ky[8],ky[12]) CEU(ky[9],ky[13]) CEU(ky[10],ky[14]) CEU(ky[11],ky[15])
        CEU(ky[2],ky[4]) CEU(ky[3],ky[5]) CEU(ky[10],ky[12]) CEU(ky[11],ky[13])
        CEU(ky[1],ky[2]) CEU(ky[3],ky[4]) CEU(ky[5],ky[6])
        CEU(ky[9],ky[10]) CEU(ky[11],ky[12]) CEU(ky[13],ky[14])
        CEU(ky[0],ky[8]) CEU(ky[1],ky[9]) CEU(ky[2],ky[10]) CEU(ky[3],ky[11])
        CEU(ky[4],ky[12]) CEU(ky[5],ky[13]) CEU(ky[6],ky[14]) CEU(ky[7],ky[15])
        CEU(ky[4],ky[8]) CEU(ky[5],ky[9]) CEU(ky[6],ky[10]) CEU(ky[7],ky[11])
        CEU(ky[2],ky[4]) CEU(ky[3],ky[5]) CEU(ky[6],ky[8]) CEU(ky[7],ky[9])
        CEU(ky[10],ky[12]) CEU(ky[11],ky[13])
        CEU(ky[1],ky[2]) CEU(ky[3],ky[4]) CEU(ky[5],ky[6]) CEU(ky[7],ky[8])
        CEU(ky[9],ky[10]) CEU(ky[11],ky[12]) CEU(ky[13],ky[14])

        // ---- Shoelace over sorted valid vertices ----
        float area2 = 0.f;
        float v0x = 0.f, v0y = 0.f, pvx = 0.f, pvy = 0.f;
#pragma unroll 16
        for (int j = 0; j < 16; j++) {
            if (j >= kc) break;
            float2 v = sverts[ky[j] & 15u][tid];
            if (j == 0) { v0x = v.x; v0y = v.y; }
            else area2 += pvx * v.y - pvy * v.x;
            pvx = v.x; pvy = v.y;
        }
        area2 += pvx * v0y - pvy * v0x;
        float inter = fabsf(area2) * 0.5f;

        float iou = __fdividef(inter, pw * ph + tw * th - inter);
        iou = fmaxf(iou, 1e-6f);

        // ---- Residual: x-sort corners of each box (5-CE networks) ----
        float ax0 = c1x[0], ay0 = c1y[0], ax1 = c1x[1], ay1 = c1y[1];
        float ax2 = c1x[2], ay2 = c1y[2], ax3 = c1x[3], ay3 = c1y[3];
        CE(ax0, ay0, ax1, ay1) CE(ax2, ay2, ax3, ay3)
        CE(ax0, ay0, ax2, ay2) CE(ax1, ay1, ax3, ay3)
        CE(ax1, ay1, ax2, ay2)
        float bx0 = c2x[0], by0 = c2y[0], bx1 = c2x[1], by1 = c2y[1];
        float bx2 = c2x[2], by2 = c2y[2], bx3 = c2x[3], by3 = c2y[3];
        CE(bx0, by0, bx1, by1) CE(bx2, by2, bx3, by3)
        CE(bx0, by0, bx2, by2) CE(bx1, by1, bx3, by3)
        CE(bx1, by1, bx2, by2)

        float d0 = bx0 - ax0;
        float d = 2.f * d0 * d0;
        float q1x = ax1 - bx1, q1y = ay1 - by1;
        float q2x = ax2 - bx2, q2y = ay2 - by2;
        float q3x = ax3 - bx3, q3y = ay3 - by3;
        d += q1x * q1x + q1y * q1y;
        d += q2x * q2x + q2y * q2y;
        d += q3x * q3x + q3y * q3y;
        float res = d * (1.f / (4.f * 1024.f * 1024.f));
        loss += 1.f - iou + res;
    }

    // ---- Block reduction -> per-block partial ----
#pragma unroll
    for (int o = 16; o > 0; o >>= 1)
        loss += __shfl_down_sync(0xffffffffu, loss, o);
    __shared__ float ssum[8];
    __shared__ bool is_last;
    int lane = threadIdx.x & 31, wid = threadIdx.x >> 5;
    if (lane == 0) ssum[wid] = loss;
    __syncthreads();
    if (threadIdx.x == 0) {
        float v = 0.f;
#pragma unroll
        for (int w = 0; w < 8; w++) v += ssum[w];
        g_part[blockIdx.x] = v;
        __threadfence();
        unsigned old = atomicAdd(&g_ctr, 1u);
        is_last = (old == (unsigned)(gridDim.x - 1));
    }
    __syncthreads();

    // ---- Last block finalizes (single kernel, graph-replay safe) ----
    if (is_last) {
        double s = 0.0;
        for (int j = threadIdx.x; j < nblk; j += blockDim.x)
            s += (double)__ldcg(&g_part[j]);
        __shared__ double sd[BT];
        sd[threadIdx.x] = s;
        __syncthreads();
#pragma unroll
        for (int o = BT / 2; o > 0; o >>= 1) {
            if (threadIdx.x < o) sd[threadIdx.x] += sd[threadIdx.x + o];
            __syncthreads();
        }
        if (threadIdx.x == 0) {
            out[0] = (float)(sd[0] / (double)n);
            g_ctr = 0;  // reset for next graph replay
        }
    }
}

extern "C" void kernel_launch(void* const* d_in, const int* in_sizes, int n_in,
                              void* d_out, int out_size)
{
    (void)n_in; (void)out_size;
    const float* pred = (const float*)d_in[0];
    const float* target = (const float*)d_in[1];
    int n = in_sizes[0] / 5;
    int blocks = (n + BT - 1) / BT;
    if (blocks > MAXBLK) blocks = MAXBLK;  // grid-stride covers remainder
    k_loss<<<blocks, BT>>>(pred, target, (float*)d_out, n, blocks);
}